// round 1
// baseline (speedup 1.0000x reference)
#include <cuda_runtime.h>
#include <math.h>

// Problem constants
#define NB 64
#define NA 256
#define NROWS (NB*NA)          // 16384 (b,i) rows
#define AE 20                  // atomemb dim
#define DF 25                  // gaussian features
#define VW_COLS 45             // AE + DF

// Table config: 1024 cells over [0,5), 1025 nodes, 20 outputs, stride 21 (odd -> LDS conflicts only on idx%32 collision)
#define TBL 1024
#define TSTRIDE 21
#define TBL_FLOATS ((TBL+1)*TSTRIDE)   // 21525 floats = 86.1 KB

// Device scratch (no allocations allowed)
__device__ float d_table[TBL_FLOATS];
__device__ float d_base [NROWS*AE];
__device__ float d_cfeat[NROWS*AE];
__device__ float d_weff [AE];
__device__ float d_beff;
__device__ float d_erow [NROWS];

// tanh via ex2.approx + rcp.approx: ~1e-6 abs error, handles saturation (inf -> 1, 0 -> -1)
__device__ __forceinline__ float fast_tanh(float x) {
    float e;
    asm("ex2.approx.f32 %0, %1;" : "=f"(e) : "f"(x * 2.88539008177792681f)); // e^{2x}
    float r;
    asm("rcp.approx.f32 %0, %1;" : "=f"(r) : "f"(e + 1.0f));
    return fmaf(-2.0f, r, 1.0f);
}

// ---------- prep: Weff = W2 @ W1, beff = W2@b1 + b2 ----------
__global__ void k_weff(const float* __restrict__ W1, const float* __restrict__ b1,
                       const float* __restrict__ W2, const float* __restrict__ b2) {
    int t = threadIdx.x;
    if (t < AE) {
        float s = 0.f;
        #pragma unroll
        for (int m = 0; m < 10; m++) s += W2[m] * W1[m*AE + t];
        d_weff[t] = s;
    }
    if (t == AE) {
        float s = b2[0];
        #pragma unroll
        for (int m = 0; m < 10; m++) s += W2[m] * b1[m];
        d_beff = s;
    }
}

// ---------- prep: g_o(d) table: sum_k Vw[o][20+k] * exp(-2 (d - 0.2k)^2) ----------
__global__ void k_table(const float* __restrict__ Vw) {
    int idx = blockIdx.x * blockDim.x + threadIdx.x;
    if (idx >= (TBL+1)*AE) return;
    int t = idx / AE;
    int o = idx - t*AE;
    float d = (float)t * (5.0f / (float)TBL);
    float s = 0.f;
    #pragma unroll
    for (int k = 0; k < DF; k++) {
        float x = d - 0.2f * (float)k;
        s += Vw[o*VW_COLS + AE + k] * __expf(-2.0f * x * x);
    }
    d_table[t*TSTRIDE + o] = s;
}

// ---------- prep: per-(b,i) cfeat and base = cfeat @ Vw[:, :20]^T + Vb ----------
__global__ void k_rows(const int* __restrict__ z, const float* __restrict__ emb,
                       const float* __restrict__ Vw, const float* __restrict__ Vb) {
    int idx = blockIdx.x * blockDim.x + threadIdx.x;
    if (idx >= NROWS*AE) return;
    int row = idx / AE;
    int o   = idx - row*AE;
    int zi  = z[row];
    float m = (zi != 0) ? 1.f : 0.f;
    d_cfeat[idx] = m * emb[zi*AE + o];
    float b = Vb[o];
    #pragma unroll
    for (int f = 0; f < AE; f++)
        b = fmaf(m * emb[zi*AE + f], Vw[o*VW_COLS + f], b);
    d_base[idx] = b;
}

// ---------- main: one warp per (b,i) row; lerp table, tanh, reduce over j ----------
__global__ void __launch_bounds__(384, 2)
k_main(const float* __restrict__ dist, const int* __restrict__ z) {
    extern __shared__ float tab[];
    const int tid = threadIdx.x;
    for (int i = tid; i < TBL_FLOATS; i += blockDim.x) tab[i] = d_table[i];
    __syncthreads();

    const int lane = tid & 31;
    const int nwarps = gridDim.x * (blockDim.x >> 5);
    int gw = blockIdx.x * (blockDim.x >> 5) + (tid >> 5);

    for (int row = gw; row < NROWS; row += nwarps) {
        float base[AE], acc[AE];
        const float* bp = d_base + row*AE;
        #pragma unroll
        for (int o = 0; o < AE; o++) { base[o] = __ldg(bp + o); acc[o] = 0.f; }

        const float* drow = dist + (size_t)row * NA;
        #pragma unroll
        for (int jt = 0; jt < NA/32; jt++) {
            float d  = drow[jt*32 + lane];
            float xf = d * ((float)TBL / 5.0f);
            int   ti = (int)xf;
            ti = ti < 0 ? 0 : (ti > TBL-1 ? TBL-1 : ti);
            float fr = xf - (float)ti;
            const float* r0 = tab + ti * TSTRIDE;
            #pragma unroll
            for (int o = 0; o < AE; o++) {
                float a  = r0[o];
                float bv = r0[TSTRIDE + o];
                float g  = fmaf(fr, bv - a, a);
                acc[o] += fast_tanh(base[o] + g);
            }
        }

        // warp reduce each of the 20 accumulators
        #pragma unroll
        for (int o = 0; o < AE; o++) {
            #pragma unroll
            for (int off = 16; off; off >>= 1)
                acc[o] += __shfl_xor_sync(0xffffffffu, acc[o], off);
        }

        if (lane == 0) {
            float m = (z[row] != 0) ? 1.f : 0.f;
            float e = d_beff;
            const float* cf = d_cfeat + row*AE;
            #pragma unroll
            for (int o = 0; o < AE; o++) {
                float c = (cf[o] + acc[o]) * m;
                e = fmaf(d_weff[o], fast_tanh(c), e);
            }
            d_erow[row] = e;
        }
    }
}

// ---------- final: out[b] = sum_i e[b,i] (deterministic tree reduce) ----------
__global__ void k_out(float* __restrict__ out) {
    __shared__ float sh[8];
    int b = blockIdx.x, t = threadIdx.x;
    float v = d_erow[b*NA + t];
    #pragma unroll
    for (int off = 16; off; off >>= 1) v += __shfl_xor_sync(0xffffffffu, v, off);
    if ((t & 31) == 0) sh[t >> 5] = v;
    __syncthreads();
    if (t == 0) {
        float s = 0.f;
        #pragma unroll
        for (int i = 0; i < 8; i++) s += sh[i];
        out[b] = s;
    }
}

extern "C" void kernel_launch(void* const* d_in, const int* in_sizes, int n_in,
                              void* d_out, int out_size) {
    const int*   z    = (const int*)  d_in[0];
    const float* dist = (const float*)d_in[1];
    const float* emb  = (const float*)d_in[2];
    const float* Vw   = (const float*)d_in[3];
    const float* Vb   = (const float*)d_in[4];
    const float* W1   = (const float*)d_in[5];
    const float* b1   = (const float*)d_in[6];
    const float* W2   = (const float*)d_in[7];
    const float* b2   = (const float*)d_in[8];
    float* out = (float*)d_out;
    (void)in_sizes; (void)n_in; (void)out_size;

    // allow >48KB dynamic smem (idempotent; not an allocation)
    cudaFuncSetAttribute(k_main, cudaFuncAttributeMaxDynamicSharedMemorySize, TBL_FLOATS * 4);

    k_weff <<<1, 64>>>(W1, b1, W2, b2);
    k_table<<<((TBL+1)*AE + 127)/128, 128>>>(Vw);
    k_rows <<<(NROWS*AE + 127)/128, 128>>>(z, emb, Vw, Vb);
    k_main <<<304, 384, TBL_FLOATS * 4>>>(dist, z);
    k_out  <<<NB, 256>>>(out);
}

// round 2
// speedup vs baseline: 1.3306x; 1.3306x over previous
#include <cuda_runtime.h>
#include <cuda_fp16.h>
#include <math.h>

// Problem constants
#define NB 64
#define NA 256
#define NROWS (NB*NA)          // 16384 (b,i) rows
#define AE 20                  // atomemb dim
#define DF 25                  // gaussian features
#define VW_COLS 45             // AE + DF

// Table: 1024 cells over [0,5), 1025 node rows, 20 outputs packed as 10 half2
// words + 1 pad word => stride 11 (odd in 32-bit words -> full bank residues)
#define TBL 1024
#define TW 11
#define TBL_WORDS ((TBL+1)*TW)   // 11275 words = 45.1 KB

#define CTANH 2.885390081777926814f   // 2/ln2 : e^{2x} = 2^{x*CTANH}

// Device scratch (no allocations allowed)
__device__ unsigned d_tableh[TBL_WORDS];
__device__ float d_basec[NROWS*AE];   // (cfeat @ Vw1^T + Vb) * CTANH
__device__ float d_cfeat[NROWS*AE];
__device__ float d_weff [AE];
__device__ float d_beff;
__device__ float d_erow [NROWS];

// accurate tanh: ex2.approx + rcp.approx (~1e-6 abs error)
__device__ __forceinline__ float fast_tanh(float x) {
    float e;
    asm("ex2.approx.f32 %0, %1;" : "=f"(e) : "f"(x * CTANH));
    float r;
    asm("rcp.approx.f32 %0, %1;" : "=f"(r) : "f"(e + 1.0f));
    return fmaf(-2.0f, r, 1.0f);
}

__device__ __forceinline__ float ex2f(float x) {
    float e; asm("ex2.approx.f32 %0, %1;" : "=f"(e) : "f"(x)); return e;
}
__device__ __forceinline__ float rcpf(float x) {
    float r; asm("rcp.approx.f32 %0, %1;" : "=f"(r) : "f"(x)); return r;
}

// ---------- prep: Weff = W2 @ W1, beff = W2@b1 + b2 ----------
__global__ void k_weff(const float* __restrict__ W1, const float* __restrict__ b1,
                       const float* __restrict__ W2, const float* __restrict__ b2) {
    int t = threadIdx.x;
    if (t < AE) {
        float s = 0.f;
        #pragma unroll
        for (int m = 0; m < 10; m++) s += W2[m] * W1[m*AE + t];
        d_weff[t] = s;
    }
    if (t == AE) {
        float s = b2[0];
        #pragma unroll
        for (int m = 0; m < 10; m++) s += W2[m] * b1[m];
        d_beff = s;
    }
}

// ---------- prep: g_o(d) table (half2 pairs) ----------
__global__ void k_table(const float* __restrict__ Vw) {
    int idx = blockIdx.x * blockDim.x + threadIdx.x;
    if (idx >= (TBL+1)*10) return;
    int t = idx / 10;
    int w = idx - t*10;
    float d = (float)t * (5.0f / (float)TBL);
    float g[2];
    #pragma unroll
    for (int p = 0; p < 2; p++) {
        int o = 2*w + p;
        float s = 0.f;
        #pragma unroll
        for (int k = 0; k < DF; k++) {
            float x = d - 0.2f * (float)k;
            s += Vw[o*VW_COLS + AE + k] * __expf(-2.0f * x * x);
        }
        g[p] = s;
    }
    __half2 h = __floats2half2_rn(g[0], g[1]);
    d_tableh[t*TW + w] = *(unsigned*)&h;
}

// ---------- prep: per-(b,i) cfeat and basec = (cfeat @ Vw1^T + Vb)*CTANH ----------
__global__ void k_rows(const int* __restrict__ z, const float* __restrict__ emb,
                       const float* __restrict__ Vw, const float* __restrict__ Vb) {
    int idx = blockIdx.x * blockDim.x + threadIdx.x;
    if (idx >= NROWS*AE) return;
    int row = idx / AE;
    int o   = idx - row*AE;
    int zi  = z[row];
    float m = (zi != 0) ? 1.f : 0.f;
    d_cfeat[idx] = m * emb[zi*AE + o];
    float b = Vb[o];
    #pragma unroll
    for (int f = 0; f < AE; f++)
        b = fmaf(m * emb[zi*AE + f], Vw[o*VW_COLS + f], b);
    d_basec[idx] = b * CTANH;
}

// ---------- main: one warp per (b,i) row ----------
__global__ void __launch_bounds__(384, 2)
k_main(const float* __restrict__ dist, const int* __restrict__ z) {
    extern __shared__ unsigned tabw[];
    const int tid = threadIdx.x;
    const unsigned* gt = d_tableh;
    for (int i = tid; i < TBL_WORDS; i += blockDim.x) tabw[i] = gt[i];
    __syncthreads();

    const int lane = tid & 31;
    const int nwarps = gridDim.x * (blockDim.x >> 5);
    int gw = blockIdx.x * (blockDim.x >> 5) + (tid >> 5);

    for (int row = gw; row < NROWS; row += nwarps) {
        float bc[AE], acc[AE];
        const float* bp = d_basec + row*AE;
        #pragma unroll
        for (int o = 0; o < AE; o++) { bc[o] = __ldg(bp + o); acc[o] = 0.f; }

        const float* drow = dist + (size_t)row * NA;
        #pragma unroll
        for (int jt = 0; jt < NA/32; jt++) {
            float d  = drow[jt*32 + lane];
            float xf = d * ((float)TBL / 5.0f);
            int   ti = (int)xf;
            ti = ti < 0 ? 0 : (ti > TBL-1 ? TBL-1 : ti);
            float fr  = xf - (float)ti;
            float frC = fr * CTANH;
            const unsigned* r0 = tabw + ti * TW;
            #pragma unroll
            for (int w = 0; w < 10; w++) {
                __half2 ha = *(const __half2*)(r0 + w);
                __half2 hb = *(const __half2*)(r0 + TW + w);
                float2 a = __half22float2(ha);
                float2 b = __half22float2(hb);
                // t = CTANH*(base + a + fr*(b-a))
                float t0 = fmaf(frC, b.x - a.x, fmaf(a.x, CTANH, bc[2*w  ]));
                float t1 = fmaf(frC, b.y - a.y, fmaf(a.y, CTANH, bc[2*w+1]));
                float y0 = ex2f(t0) + 1.0f;
                float y1 = ex2f(t1) + 1.0f;
                float rp = rcpf(y0 * y1);        // batched reciprocal pair
                acc[2*w  ] = fmaf(rp, y1, acc[2*w  ]);   // += 1/y0
                acc[2*w+1] = fmaf(rp, y0, acc[2*w+1]);   // += 1/y1
            }
        }

        // warp reduce each accumulator (sum of r over all 256 j)
        #pragma unroll
        for (int o = 0; o < AE; o++) {
            #pragma unroll
            for (int off = 16; off; off >>= 1)
                acc[o] += __shfl_xor_sync(0xffffffffu, acc[o], off);
        }

        if (lane == 0) {
            float m = (z[row] != 0) ? 1.f : 0.f;
            float e = d_beff;
            const float* cf = d_cfeat + row*AE;
            #pragma unroll
            for (int o = 0; o < AE; o++) {
                // agg_o = 256 - 2*sum(r);  c = (cfeat + agg)*mask
                float c = (cf[o] + fmaf(-2.0f, acc[o], 256.0f)) * m;
                e = fmaf(d_weff[o], fast_tanh(c), e);
            }
            d_erow[row] = e;
        }
    }
}

// ---------- final: out[b] = sum_i e[b,i] ----------
__global__ void k_out(float* __restrict__ out) {
    __shared__ float sh[8];
    int b = blockIdx.x, t = threadIdx.x;
    float v = d_erow[b*NA + t];
    #pragma unroll
    for (int off = 16; off; off >>= 1) v += __shfl_xor_sync(0xffffffffu, v, off);
    if ((t & 31) == 0) sh[t >> 5] = v;
    __syncthreads();
    if (t == 0) {
        float s = 0.f;
        #pragma unroll
        for (int i = 0; i < 8; i++) s += sh[i];
        out[b] = s;
    }
}

extern "C" void kernel_launch(void* const* d_in, const int* in_sizes, int n_in,
                              void* d_out, int out_size) {
    const int*   z    = (const int*)  d_in[0];
    const float* dist = (const float*)d_in[1];
    const float* emb  = (const float*)d_in[2];
    const float* Vw   = (const float*)d_in[3];
    const float* Vb   = (const float*)d_in[4];
    const float* W1   = (const float*)d_in[5];
    const float* b1   = (const float*)d_in[6];
    const float* W2   = (const float*)d_in[7];
    const float* b2   = (const float*)d_in[8];
    float* out = (float*)d_out;
    (void)in_sizes; (void)n_in; (void)out_size;

    cudaFuncSetAttribute(k_main, cudaFuncAttributeMaxDynamicSharedMemorySize,
                         TBL_WORDS * 4);

    k_weff <<<1, 64>>>(W1, b1, W2, b2);
    k_table<<<((TBL+1)*10 + 127)/128, 128>>>(Vw);
    k_rows <<<(NROWS*AE + 127)/128, 128>>>(z, emb, Vw, Vb);
    k_main <<<296, 384, TBL_WORDS * 4>>>(dist, z);
    k_out  <<<NB, 256>>>(out);
}

// round 3
// speedup vs baseline: 1.8212x; 1.3687x over previous
#include <cuda_runtime.h>
#include <cuda_fp16.h>
#include <math.h>

// Problem constants
#define NB 64
#define NA 256
#define NROWS (NB*NA)          // 16384 (b,i) rows
#define AE 20                  // atomemb dim
#define DF 25                  // gaussian features
#define VW_COLS 45             // AE + DF

// Nearest-neighbor exp-table: 2049 nodes over [0,5], 20 outputs packed as
// 10 half2 words + 1 pad => stride 11 words (odd -> all 32 bank residues)
#define TBL 2048
#define TW 11
#define TBL_WORDS ((TBL+1)*TW)   // 22539 words = 90.2 KB

#define CTANH 2.885390081777926814f   // 2/ln2

// Device scratch (no allocations allowed)
__device__ unsigned d_tableh[TBL_WORDS];  // half2: E_o(d) = exp(2*g_o(d))
__device__ float d_ebf  [NROWS*AE];       // exp(2*base_o) per row, fp32
__device__ float d_cfeat[NROWS*AE];
__device__ float d_weff [AE];
__device__ float d_beff;
__device__ float d_erow [NROWS];

__device__ __forceinline__ float fast_tanh(float x) {
    float e;
    asm("ex2.approx.f32 %0, %1;" : "=f"(e) : "f"(x * CTANH));
    float r;
    asm("rcp.approx.f32 %0, %1;" : "=f"(r) : "f"(e + 1.0f));
    return fmaf(-2.0f, r, 1.0f);
}
__device__ __forceinline__ float rcpf(float x) {
    float r; asm("rcp.approx.f32 %0, %1;" : "=f"(r) : "f"(x)); return r;
}

// ---------- prep: Weff = W2 @ W1, beff = W2@b1 + b2 ----------
__global__ void k_weff(const float* __restrict__ W1, const float* __restrict__ b1,
                       const float* __restrict__ W2, const float* __restrict__ b2) {
    int t = threadIdx.x;
    if (t < AE) {
        float s = 0.f;
        #pragma unroll
        for (int m = 0; m < 10; m++) s += W2[m] * W1[m*AE + t];
        d_weff[t] = s;
    }
    if (t == AE) {
        float s = b2[0];
        #pragma unroll
        for (int m = 0; m < 10; m++) s += W2[m] * b1[m];
        d_beff = s;
    }
}

// ---------- prep: E table (half2 pairs): exp(2 * g_o(d)) ----------
__global__ void k_table(const float* __restrict__ Vw) {
    int idx = blockIdx.x * blockDim.x + threadIdx.x;
    if (idx >= (TBL+1)*10) return;
    int t = idx / 10;
    int w = idx - t*10;
    float d = (float)t * (5.0f / (float)TBL);
    float g[2];
    #pragma unroll
    for (int p = 0; p < 2; p++) {
        int o = 2*w + p;
        float s = 0.f;
        #pragma unroll
        for (int k = 0; k < DF; k++) {
            float x = d - 0.2f * (float)k;
            s += Vw[o*VW_COLS + AE + k] * __expf(-2.0f * x * x);
        }
        g[p] = __expf(2.0f * s);
    }
    __half2 h = __floats2half2_rn(g[0], g[1]);
    d_tableh[t*TW + w] = *(unsigned*)&h;
}

// ---------- prep: cfeat and Eb = exp(2*(cfeat @ Vw1^T + Vb)) ----------
__global__ void k_rows(const int* __restrict__ z, const float* __restrict__ emb,
                       const float* __restrict__ Vw, const float* __restrict__ Vb) {
    int idx = blockIdx.x * blockDim.x + threadIdx.x;
    if (idx >= NROWS*AE) return;
    int row = idx / AE;
    int o   = idx - row*AE;
    int zi  = z[row];
    float m = (zi != 0) ? 1.f : 0.f;
    d_cfeat[idx] = m * emb[zi*AE + o];
    float b = Vb[o];
    #pragma unroll
    for (int f = 0; f < AE; f++)
        b = fmaf(m * emb[zi*AE + f], Vw[o*VW_COLS + f], b);
    d_ebf[idx] = __expf(2.0f * b);
}

// ---------- main: one warp per (b,i) row ----------
__global__ void __launch_bounds__(384, 2)
k_main(const float* __restrict__ dist, const int* __restrict__ z) {
    extern __shared__ unsigned tabw[];
    const int tid = threadIdx.x;
    const unsigned* gt = d_tableh;
    for (int i = tid; i < TBL_WORDS; i += blockDim.x) tabw[i] = gt[i];
    __syncthreads();

    const int lane = tid & 31;
    const int nwarps = gridDim.x * (blockDim.x >> 5);
    int gw = blockIdx.x * (blockDim.x >> 5) + (tid >> 5);

    for (int row = gw; row < NROWS; row += nwarps) {
        float eb[AE], acc[AE];
        const float* ep = d_ebf + row*AE;
        #pragma unroll
        for (int o = 0; o < AE; o++) { eb[o] = __ldg(ep + o); acc[o] = 0.f; }

        const float* drow = dist + (size_t)row * NA;
        #pragma unroll
        for (int jt = 0; jt < NA/32; jt++) {
            float d  = drow[jt*32 + lane];
            int   ti = __float2int_rn(d * ((float)TBL / 5.0f));
            const unsigned* r0 = tabw + ti * TW;
            #pragma unroll
            for (int w = 0; w < 10; w += 2) {
                __half2 E0 = *(const __half2*)(r0 + w);
                __half2 E1 = *(const __half2*)(r0 + w + 1);
                float2 e0 = __half22float2(E0);
                float2 e1 = __half22float2(E1);
                float y0 = fmaf(e0.x, eb[2*w  ], 1.0f);
                float y1 = fmaf(e0.y, eb[2*w+1], 1.0f);
                float y2 = fmaf(e1.x, eb[2*w+2], 1.0f);
                float y3 = fmaf(e1.y, eb[2*w+3], 1.0f);
                float t01 = y0 * y1;
                float t23 = y2 * y3;
                float r   = rcpf(t01 * t23);
                float r01 = r * t23;                 // 1/(y0*y1)
                float r23 = r * t01;                 // 1/(y2*y3)
                acc[2*w  ] = fmaf(r01, y1, acc[2*w  ]);
                acc[2*w+1] = fmaf(r01, y0, acc[2*w+1]);
                acc[2*w+2] = fmaf(r23, y3, acc[2*w+2]);
                acc[2*w+3] = fmaf(r23, y2, acc[2*w+3]);
            }
        }

        // warp reduce each accumulator (sum of r over all 256 j)
        #pragma unroll
        for (int o = 0; o < AE; o++) {
            #pragma unroll
            for (int off = 16; off; off >>= 1)
                acc[o] += __shfl_xor_sync(0xffffffffu, acc[o], off);
        }

        if (lane == 0) {
            float m = (z[row] != 0) ? 1.f : 0.f;
            float e = d_beff;
            const float* cf = d_cfeat + row*AE;
            #pragma unroll
            for (int o = 0; o < AE; o++) {
                // agg_o = 256 - 2*sum(r);  c = (cfeat + agg)*mask
                float c = (cf[o] + fmaf(-2.0f, acc[o], 256.0f)) * m;
                e = fmaf(d_weff[o], fast_tanh(c), e);
            }
            d_erow[row] = e;
        }
    }
}

// ---------- final: out[b] = sum_i e[b,i] ----------
__global__ void k_out(float* __restrict__ out) {
    __shared__ float sh[8];
    int b = blockIdx.x, t = threadIdx.x;
    float v = d_erow[b*NA + t];
    #pragma unroll
    for (int off = 16; off; off >>= 1) v += __shfl_xor_sync(0xffffffffu, v, off);
    if ((t & 31) == 0) sh[t >> 5] = v;
    __syncthreads();
    if (t == 0) {
        float s = 0.f;
        #pragma unroll
        for (int i = 0; i < 8; i++) s += sh[i];
        out[b] = s;
    }
}

extern "C" void kernel_launch(void* const* d_in, const int* in_sizes, int n_in,
                              void* d_out, int out_size) {
    const int*   z    = (const int*)  d_in[0];
    const float* dist = (const float*)d_in[1];
    const float* emb  = (const float*)d_in[2];
    const float* Vw   = (const float*)d_in[3];
    const float* Vb   = (const float*)d_in[4];
    const float* W1   = (const float*)d_in[5];
    const float* b1   = (const float*)d_in[6];
    const float* W2   = (const float*)d_in[7];
    const float* b2   = (const float*)d_in[8];
    float* out = (float*)d_out;
    (void)in_sizes; (void)n_in; (void)out_size;

    cudaFuncSetAttribute(k_main, cudaFuncAttributeMaxDynamicSharedMemorySize,
                         TBL_WORDS * 4);

    k_weff <<<1, 64>>>(W1, b1, W2, b2);
    k_table<<<((TBL+1)*10 + 127)/128, 128>>>(Vw);
    k_rows <<<(NROWS*AE + 127)/128, 128>>>(z, emb, Vw, Vb);
    k_main <<<296, 384, TBL_WORDS * 4>>>(dist, z);
    k_out  <<<NB, 256>>>(out);
}

// round 4
// speedup vs baseline: 1.9198x; 1.0541x over previous
#include <cuda_runtime.h>
#include <cuda_fp16.h>
#include <math.h>

// Problem constants
#define NB 64
#define NA 256
#define NROWS (NB*NA)          // 16384 (b,i) rows
#define AE 20                  // atomemb dim
#define DF 25                  // gaussian features
#define VW_COLS 45             // AE + DF

// Nearest-neighbor exp-table: 1537 node rows over [0,5], 20 outputs packed as
// 10 half2 words + 1 pad => stride 11 words (odd -> all 32 bank residues)
#define TBL 1536
#define TW 11
#define TBL_WORDS ((TBL+1)*TW)   // 16907 words = 67.6 KB

#define CTANH 2.885390081777926814f   // 2/ln2

// Device scratch (no allocations allowed)
__device__ unsigned d_tableh[TBL_WORDS];  // half2: E_o(d) = exp(2*g_o(d))
__device__ float d_ebf  [NROWS*AE];       // exp(2*base_o) per row, fp32
__device__ float d_cfeat[NROWS*AE];
__device__ float d_weff [AE];
__device__ float d_beff;
__device__ float d_epart[NROWS*2];        // two partial energies per row

__device__ __forceinline__ float fast_tanh(float x) {
    float e;
    asm("ex2.approx.f32 %0, %1;" : "=f"(e) : "f"(x * CTANH));
    float r;
    asm("rcp.approx.f32 %0, %1;" : "=f"(r) : "f"(e + 1.0f));
    return fmaf(-2.0f, r, 1.0f);
}
__device__ __forceinline__ float rcpf(float x) {
    float r; asm("rcp.approx.f32 %0, %1;" : "=f"(r) : "f"(x)); return r;
}

// ---------- prep: Weff = W2 @ W1, beff = W2@b1 + b2 ----------
__global__ void k_weff(const float* __restrict__ W1, const float* __restrict__ b1,
                       const float* __restrict__ W2, const float* __restrict__ b2) {
    int t = threadIdx.x;
    if (t < AE) {
        float s = 0.f;
        #pragma unroll
        for (int m = 0; m < 10; m++) s += W2[m] * W1[m*AE + t];
        d_weff[t] = s;
    }
    if (t == AE) {
        float s = b2[0];
        #pragma unroll
        for (int m = 0; m < 10; m++) s += W2[m] * b1[m];
        d_beff = s;
    }
}

// ---------- prep: E table (half2 pairs): exp(2 * g_o(d)) ----------
__global__ void k_table(const float* __restrict__ Vw) {
    int idx = blockIdx.x * blockDim.x + threadIdx.x;
    if (idx >= (TBL+1)*10) return;
    int t = idx / 10;
    int w = idx - t*10;
    float d = (float)t * (5.0f / (float)TBL);
    float g[2];
    #pragma unroll
    for (int p = 0; p < 2; p++) {
        int o = 2*w + p;
        float s = 0.f;
        #pragma unroll
        for (int k = 0; k < DF; k++) {
            float x = d - 0.2f * (float)k;
            s += Vw[o*VW_COLS + AE + k] * __expf(-2.0f * x * x);
        }
        g[p] = __expf(2.0f * s);
    }
    __half2 h = __floats2half2_rn(g[0], g[1]);
    d_tableh[t*TW + w] = *(unsigned*)&h;
}

// ---------- prep: cfeat and Eb = exp(2*(cfeat @ Vw1^T + Vb)) ----------
__global__ void k_rows(const int* __restrict__ z, const float* __restrict__ emb,
                       const float* __restrict__ Vw, const float* __restrict__ Vb) {
    int idx = blockIdx.x * blockDim.x + threadIdx.x;
    if (idx >= NROWS*AE) return;
    int row = idx / AE;
    int o   = idx - row*AE;
    int zi  = z[row];
    float m = (zi != 0) ? 1.f : 0.f;
    d_cfeat[idx] = m * emb[zi*AE + o];
    float b = Vb[o];
    #pragma unroll
    for (int f = 0; f < AE; f++)
        b = fmaf(m * emb[zi*AE + f], Vw[o*VW_COLS + f], b);
    d_ebf[idx] = __expf(2.0f * b);
}

// ---------- main: TWO warps per (b,i) row, 10 outputs each ----------
__global__ void __launch_bounds__(512, 3)
k_main(const float* __restrict__ dist, const int* __restrict__ z) {
    extern __shared__ unsigned tabw[];
    const int tid = threadIdx.x;
    const unsigned* gt = d_tableh;
    for (int i = tid; i < TBL_WORDS; i += blockDim.x) tabw[i] = gt[i];
    __syncthreads();

    const int lane = tid & 31;
    const int nwarps = gridDim.x * (blockDim.x >> 5);  // tasks stride
    int gw = blockIdx.x * (blockDim.x >> 5) + (tid >> 5);
    const int ntasks = NROWS * 2;

    for (int task = gw; task < ntasks; task += nwarps) {
        const int row  = task >> 1;
        const int half = task & 1;         // which 10 outputs
        const int ob   = half * 10;        // output base
        const int wb   = half * 5;         // word base in table row

        float eb[10], acc[10];
        const float* ep = d_ebf + row*AE + ob;
        #pragma unroll
        for (int o = 0; o < 10; o++) { eb[o] = __ldg(ep + o); acc[o] = 0.f; }

        const float* drow = dist + (size_t)row * NA;
        #pragma unroll
        for (int jt = 0; jt < NA/32; jt++) {
            float d  = drow[jt*32 + lane];
            int   ti = __float2int_rn(d * ((float)TBL / 5.0f));
            ti = min(ti, TBL);
            const unsigned* r0 = tabw + ti * TW + wb;
            float2 e0 = __half22float2(*(const __half2*)(r0 + 0));
            float2 e1 = __half22float2(*(const __half2*)(r0 + 1));
            float2 e2 = __half22float2(*(const __half2*)(r0 + 2));
            float2 e3 = __half22float2(*(const __half2*)(r0 + 3));
            float2 e4 = __half22float2(*(const __half2*)(r0 + 4));

            float y0 = fmaf(e0.x, eb[0], 1.0f);
            float y1 = fmaf(e0.y, eb[1], 1.0f);
            float y2 = fmaf(e1.x, eb[2], 1.0f);
            float y3 = fmaf(e1.y, eb[3], 1.0f);
            {
                float t01 = y0 * y1, t23 = y2 * y3;
                float r   = rcpf(t01 * t23);
                float r01 = r * t23, r23 = r * t01;
                acc[0] = fmaf(r01, y1, acc[0]);
                acc[1] = fmaf(r01, y0, acc[1]);
                acc[2] = fmaf(r23, y3, acc[2]);
                acc[3] = fmaf(r23, y2, acc[3]);
            }
            float y4 = fmaf(e2.x, eb[4], 1.0f);
            float y5 = fmaf(e2.y, eb[5], 1.0f);
            float y6 = fmaf(e3.x, eb[6], 1.0f);
            float y7 = fmaf(e3.y, eb[7], 1.0f);
            {
                float t01 = y4 * y5, t23 = y6 * y7;
                float r   = rcpf(t01 * t23);
                float r01 = r * t23, r23 = r * t01;
                acc[4] = fmaf(r01, y5, acc[4]);
                acc[5] = fmaf(r01, y4, acc[5]);
                acc[6] = fmaf(r23, y7, acc[6]);
                acc[7] = fmaf(r23, y6, acc[7]);
            }
            float y8 = fmaf(e4.x, eb[8], 1.0f);
            float y9 = fmaf(e4.y, eb[9], 1.0f);
            {
                float t = y8 * y9;
                float r = rcpf(t);
                acc[8] = fmaf(r, y9, acc[8]);
                acc[9] = fmaf(r, y8, acc[9]);
            }
        }

        // warp reduce each accumulator (sum of r over all 256 j)
        #pragma unroll
        for (int o = 0; o < 10; o++) {
            #pragma unroll
            for (int off = 16; off; off >>= 1)
                acc[o] += __shfl_xor_sync(0xffffffffu, acc[o], off);
        }

        if (lane == 0) {
            float m = (z[row] != 0) ? 1.f : 0.f;
            float e = (half == 0) ? d_beff : 0.0f;
            const float* cf = d_cfeat + row*AE + ob;
            const float* wf = d_weff + ob;
            #pragma unroll
            for (int o = 0; o < 10; o++) {
                // agg_o = 256 - 2*sum(r);  c = (cfeat + agg)*mask
                float c = (cf[o] + fmaf(-2.0f, acc[o], 256.0f)) * m;
                e = fmaf(wf[o], fast_tanh(c), e);
            }
            d_epart[row*2 + half] = e;
        }
    }
}

// ---------- final: out[b] = sum over 512 partials ----------
__global__ void k_out(float* __restrict__ out) {
    __shared__ float sh[16];
    int b = blockIdx.x, t = threadIdx.x;
    float v = d_epart[b*512 + t];
    #pragma unroll
    for (int off = 16; off; off >>= 1) v += __shfl_xor_sync(0xffffffffu, v, off);
    if ((t & 31) == 0) sh[t >> 5] = v;
    __syncthreads();
    if (t == 0) {
        float s = 0.f;
        #pragma unroll
        for (int i = 0; i < 16; i++) s += sh[i];
        out[b] = s;
    }
}

extern "C" void kernel_launch(void* const* d_in, const int* in_sizes, int n_in,
                              void* d_out, int out_size) {
    const int*   z    = (const int*)  d_in[0];
    const float* dist = (const float*)d_in[1];
    const float* emb  = (const float*)d_in[2];
    const float* Vw   = (const float*)d_in[3];
    const float* Vb   = (const float*)d_in[4];
    const float* W1   = (const float*)d_in[5];
    const float* b1   = (const float*)d_in[6];
    const float* W2   = (const float*)d_in[7];
    const float* b2   = (const float*)d_in[8];
    float* out = (float*)d_out;
    (void)in_sizes; (void)n_in; (void)out_size;

    cudaFuncSetAttribute(k_main, cudaFuncAttributeMaxDynamicSharedMemorySize,
                         TBL_WORDS * 4);

    k_weff <<<1, 64>>>(W1, b1, W2, b2);
    k_table<<<((TBL+1)*10 + 127)/128, 128>>>(Vw);
    k_rows <<<(NROWS*AE + 127)/128, 128>>>(z, emb, Vw, Vb);
    k_main <<<444, 512, TBL_WORDS * 4>>>(dist, z);
    k_out  <<<NB, 512>>>(out);
}

// round 5
// speedup vs baseline: 1.9903x; 1.0368x over previous
#include <cuda_runtime.h>
#include <cuda_fp16.h>
#include <math.h>

// Problem constants
#define NB 64
#define NA 256
#define NROWS (NB*NA)          // 16384 (b,i) rows
#define AE 20                  // atomemb dim
#define DF 25                  // gaussian features
#define VW_COLS 45             // AE + DF

// Nearest-neighbor exp-table: 1537 node rows over [0,5], 20 outputs packed as
// 10 half2 words = 40 bytes/row. 8-byte-unit stride = 5 (odd) -> LDS.64 hits
// all 16 bank-pair residues.
#define TBL 1536
#define TW 10
#define TBL_WORDS ((TBL+1)*TW)   // 15370 words = 61.5 KB

#define CTANH 2.885390081777926814f   // 2/ln2

// Device scratch (no allocations allowed)
__device__ unsigned d_tableh[TBL_WORDS];  // half2: E_o(d) = exp(2*g_o(d))
__device__ float d_ebf  [NROWS*AE];       // exp(2*base_o) per row, fp32
__device__ float d_cfeat[NROWS*AE];
__device__ float d_weff [AE];
__device__ float d_beff;
__device__ float d_erow [NROWS];

__device__ __forceinline__ float fast_tanh(float x) {
    float e;
    asm("ex2.approx.f32 %0, %1;" : "=f"(e) : "f"(x * CTANH));
    float r;
    asm("rcp.approx.f32 %0, %1;" : "=f"(r) : "f"(e + 1.0f));
    return fmaf(-2.0f, r, 1.0f);
}
__device__ __forceinline__ float rcpf(float x) {
    float r; asm("rcp.approx.f32 %0, %1;" : "=f"(r) : "f"(x)); return r;
}

// ---------- prep: Weff = W2 @ W1, beff = W2@b1 + b2 ----------
__global__ void k_weff(const float* __restrict__ W1, const float* __restrict__ b1,
                       const float* __restrict__ W2, const float* __restrict__ b2) {
    int t = threadIdx.x;
    if (t < AE) {
        float s = 0.f;
        #pragma unroll
        for (int m = 0; m < 10; m++) s += W2[m] * W1[m*AE + t];
        d_weff[t] = s;
    }
    if (t == AE) {
        float s = b2[0];
        #pragma unroll
        for (int m = 0; m < 10; m++) s += W2[m] * b1[m];
        d_beff = s;
    }
}

// ---------- prep: E table (half2 pairs): exp(2 * g_o(d)) ----------
__global__ void k_table(const float* __restrict__ Vw) {
    int idx = blockIdx.x * blockDim.x + threadIdx.x;
    if (idx >= (TBL+1)*TW) return;
    int t = idx / TW;
    int w = idx - t*TW;
    float d = (float)t * (5.0f / (float)TBL);
    float g[2];
    #pragma unroll
    for (int p = 0; p < 2; p++) {
        int o = 2*w + p;
        float s = 0.f;
        #pragma unroll
        for (int k = 0; k < DF; k++) {
            float x = d - 0.2f * (float)k;
            s += Vw[o*VW_COLS + AE + k] * __expf(-2.0f * x * x);
        }
        g[p] = __expf(2.0f * s);
    }
    __half2 h = __floats2half2_rn(g[0], g[1]);
    d_tableh[t*TW + w] = *(unsigned*)&h;
}

// ---------- prep: cfeat and Eb = exp(2*(cfeat @ Vw1^T + Vb)) ----------
__global__ void k_rows(const int* __restrict__ z, const float* __restrict__ emb,
                       const float* __restrict__ Vw, const float* __restrict__ Vb) {
    int idx = blockIdx.x * blockDim.x + threadIdx.x;
    if (idx >= NROWS*AE) return;
    int row = idx / AE;
    int o   = idx - row*AE;
    int zi  = z[row];
    float m = (zi != 0) ? 1.f : 0.f;
    d_cfeat[idx] = m * emb[zi*AE + o];
    float b = Vb[o];
    #pragma unroll
    for (int f = 0; f < AE; f++)
        b = fmaf(m * emb[zi*AE + f], Vw[o*VW_COLS + f], b);
    d_ebf[idx] = __expf(2.0f * b);
}

// process 4 outputs from one uint2 (two half2 table words)
__device__ __forceinline__ void group4(uint2 p, const float* eb, float* acc) {
    float2 a = __half22float2(*(const __half2*)&p.x);
    float2 b = __half22float2(*(const __half2*)&p.y);
    float y0 = fmaf(a.x, eb[0], 1.0f);
    float y1 = fmaf(a.y, eb[1], 1.0f);
    float y2 = fmaf(b.x, eb[2], 1.0f);
    float y3 = fmaf(b.y, eb[3], 1.0f);
    float t01 = y0 * y1, t23 = y2 * y3;
    float r   = rcpf(t01 * t23);
    float r01 = r * t23, r23 = r * t01;
    acc[0] = fmaf(r01, y1, acc[0]);
    acc[1] = fmaf(r01, y0, acc[1]);
    acc[2] = fmaf(r23, y3, acc[2]);
    acc[3] = fmaf(r23, y2, acc[3]);
}

// ---------- main: one warp per (b,i) row, LDS.64 table loads ----------
__global__ void __launch_bounds__(384, 2)
k_main(const float* __restrict__ dist, const int* __restrict__ z) {
    extern __shared__ unsigned tabw[];
    const int tid = threadIdx.x;
    const unsigned* gt = d_tableh;
    for (int i = tid; i < TBL_WORDS; i += blockDim.x) tabw[i] = gt[i];
    __syncthreads();

    const uint2* tab2 = (const uint2*)tabw;
    const int lane = tid & 31;
    const int nwarps = gridDim.x * (blockDim.x >> 5);
    int gw = blockIdx.x * (blockDim.x >> 5) + (tid >> 5);

    for (int row = gw; row < NROWS; row += nwarps) {
        float eb[AE], acc[AE];
        const float* ep = d_ebf + row*AE;
        #pragma unroll
        for (int o = 0; o < AE; o++) { eb[o] = __ldg(ep + o); acc[o] = 0.f; }

        // lane handles j = lane*8 .. lane*8+7 (coalesced float4 pair)
        const float4* drow4 = (const float4*)(dist + (size_t)row * NA + lane * 8);
        float4 dv0 = __ldg(drow4);
        float4 dv1 = __ldg(drow4 + 1);
        float dv[8] = {dv0.x, dv0.y, dv0.z, dv0.w, dv1.x, dv1.y, dv1.z, dv1.w};

        #pragma unroll
        for (int jt = 0; jt < 8; jt++) {
            int ti = __float2int_rn(dv[jt] * ((float)TBL / 5.0f));
            const uint2* r0 = tab2 + ti * 5;
            uint2 p0 = r0[0], p1 = r0[1], p2 = r0[2], p3 = r0[3], p4 = r0[4];
            group4(p0, eb +  0, acc +  0);
            group4(p1, eb +  4, acc +  4);
            group4(p2, eb +  8, acc +  8);
            group4(p3, eb + 12, acc + 12);
            group4(p4, eb + 16, acc + 16);
        }

        // warp reduce each accumulator (sum of r over all 256 j)
        #pragma unroll
        for (int o = 0; o < AE; o++) {
            #pragma unroll
            for (int off = 16; off; off >>= 1)
                acc[o] += __shfl_xor_sync(0xffffffffu, acc[o], off);
        }

        if (lane == 0) {
            float m = (z[row] != 0) ? 1.f : 0.f;
            float e = d_beff;
            const float* cf = d_cfeat + row*AE;
            #pragma unroll
            for (int o = 0; o < AE; o++) {
                // agg_o = 256 - 2*sum(r);  c = (cfeat + agg)*mask
                float c = (cf[o] + fmaf(-2.0f, acc[o], 256.0f)) * m;
                e = fmaf(d_weff[o], fast_tanh(c), e);
            }
            d_erow[row] = e;
        }
    }
}

// ---------- final: out[b] = sum_i e[b,i] ----------
__global__ void k_out(float* __restrict__ out) {
    __shared__ float sh[8];
    int b = blockIdx.x, t = threadIdx.x;
    float v = d_erow[b*NA + t];
    #pragma unroll
    for (int off = 16; off; off >>= 1) v += __shfl_xor_sync(0xffffffffu, v, off);
    if ((t & 31) == 0) sh[t >> 5] = v;
    __syncthreads();
    if (t == 0) {
        float s = 0.f;
        #pragma unroll
        for (int i = 0; i < 8; i++) s += sh[i];
        out[b] = s;
    }
}

extern "C" void kernel_launch(void* const* d_in, const int* in_sizes, int n_in,
                              void* d_out, int out_size) {
    const int*   z    = (const int*)  d_in[0];
    const float* dist = (const float*)d_in[1];
    const float* emb  = (const float*)d_in[2];
    const float* Vw   = (const float*)d_in[3];
    const float* Vb   = (const float*)d_in[4];
    const float* W1   = (const float*)d_in[5];
    const float* b1   = (const float*)d_in[6];
    const float* W2   = (const float*)d_in[7];
    const float* b2   = (const float*)d_in[8];
    float* out = (float*)d_out;
    (void)in_sizes; (void)n_in; (void)out_size;

    cudaFuncSetAttribute(k_main, cudaFuncAttributeMaxDynamicSharedMemorySize,
                         TBL_WORDS * 4);

    k_weff <<<1, 64>>>(W1, b1, W2, b2);
    k_table<<<((TBL+1)*TW + 127)/128, 128>>>(Vw);
    k_rows <<<(NROWS*AE + 127)/128, 128>>>(z, emb, Vw, Vb);
    k_main <<<296, 384, TBL_WORDS * 4>>>(dist, z);
    k_out  <<<NB, 256>>>(out);
}